// round 3
// baseline (speedup 1.0000x reference)
#include <cuda_runtime.h>

#define NB    64
#define NV    4096
#define NFEAT 16
#define NA    8
#define NP    16
#define NOUT  16
#define SPLIT 2
#define VPB   (NV / SPLIT)      // 2048 vertices per block
#define CH    256               // chunk = blockDim
#define NCH   (VPB / CH)        // 8 chunks
#define GRID  (NB * SPLIT)      // 128 blocks <= SM count -> all co-resident

// Per-(b,split) partial sums of  sum_v ew[v,a]*feat[v,p]  (128 floats each).
// Each block exclusively owns its slot and writes it unconditionally -> no zeroing kernel.
__device__ float    g_part[GRID * 128];
// Monotonic barrier counter: never reset; target derived from ticket epoch.
__device__ unsigned g_count = 0;

__global__ __launch_bounds__(256, 2) void garnet_fused(
    const float* __restrict__ data, const int* __restrict__ num_vertex,
    const float* __restrict__ W_flr, const float* __restrict__ b_flr,
    const float* __restrict__ W_s,   const float* __restrict__ b_s,
    const float* __restrict__ W_out, const float* __restrict__ b_out,
    float* __restrict__ out)
{
    __shared__ float4 sWf4[NFEAT][4];     // W_flr rows as float4
    __shared__ float4 sWs4[NFEAT][2];     // W_s rows as float4
    __shared__ float  sbf[NP];
    __shared__ float  sbs[NA];
    __shared__ float  sbo[NOUT];
    __shared__ float4 sF4[CH * 5];        // feat staging (stride 5 float4); reused as sRed
    __shared__ float  sEWst[CH * 9];      // ew staging (stride 9, conflict-free)
    __shared__ float  sAgg[NA * NP];
    __shared__ __align__(16) float sM[NA * NOUT];

    const int t     = threadIdx.x;
    const int b     = blockIdx.x / SPLIT;
    const int split = blockIdx.x % SPLIT;
    const int nv    = num_vertex[b];
    const int vbase = split * VPB;

    // ---- load weights/biases to smem ----
    if (t < 64) {
        sWf4[t >> 2][t & 3] = ((const float4*)W_flr)[t];
    } else if (t < 96) {
        const int u = t - 64;
        sWs4[u >> 1][u & 1] = ((const float4*)W_s)[u];
    } else if (t < 112) {
        sbf[t - 96] = b_flr[t - 96];
    } else if (t < 120) {
        sbs[t - 112] = b_s[t - 112];
    } else if (t < 136) {
        sbo[t - 120] = b_out[t - 120];
    }
    __syncthreads();

    // =====================================================================
    // Phase A: partial[a,p] = sum over this block's valid vertices of ew*feat
    // 32 owners (aa = o>>2, pg = o&3) x 8 slices of 32 vertices.
    // =====================================================================
    const int owner = t & 31;
    const int aa    = owner >> 2;
    const int pg    = owner & 3;
    const int slice = t >> 5;
    float4 acc = make_float4(0.f, 0.f, 0.f, 0.f);

    for (int c = 0; c < NCH; ++c) {
        const int vb = vbase + c * CH;
        if (vb >= nv) break;              // block-uniform
        const int v = vb + t;

        if (v < nv) {
            const float4* dp = (const float4*)(data + ((size_t)(b * NV + v)) * NFEAT);
            const float4 x0 = dp[0], x1 = dp[1], x2 = dp[2], x3 = dp[3];
            float x[16];
            x[0]=x0.x;  x[1]=x0.y;  x[2]=x0.z;  x[3]=x0.w;
            x[4]=x1.x;  x[5]=x1.y;  x[6]=x1.z;  x[7]=x1.w;
            x[8]=x2.x;  x[9]=x2.y;  x[10]=x2.z; x[11]=x2.w;
            x[12]=x3.x; x[13]=x3.y; x[14]=x3.z; x[15]=x3.w;

            #pragma unroll
            for (int g = 0; g < 4; ++g) {
                float s0 = sbf[g*4+0], s1 = sbf[g*4+1];
                float s2 = sbf[g*4+2], s3 = sbf[g*4+3];
                #pragma unroll
                for (int f = 0; f < 16; ++f) {
                    const float4 w = sWf4[f][g];
                    s0 += x[f]*w.x; s1 += x[f]*w.y;
                    s2 += x[f]*w.z; s3 += x[f]*w.w;
                }
                sF4[t*5 + g] = make_float4(s0, s1, s2, s3);
            }
            #pragma unroll
            for (int g = 0; g < 2; ++g) {
                float s0 = sbs[g*4+0], s1 = sbs[g*4+1];
                float s2 = sbs[g*4+2], s3 = sbs[g*4+3];
                #pragma unroll
                for (int f = 0; f < 16; ++f) {
                    const float4 w = sWs4[f][g];
                    s0 += x[f]*w.x; s1 += x[f]*w.y;
                    s2 += x[f]*w.z; s3 += x[f]*w.w;
                }
                sEWst[t*9 + g*4+0] = __expf(-s0*s0);
                sEWst[t*9 + g*4+1] = __expf(-s1*s1);
                sEWst[t*9 + g*4+2] = __expf(-s2*s2);
                sEWst[t*9 + g*4+3] = __expf(-s3*s3);
            }
        } else {
            const float4 z = make_float4(0.f, 0.f, 0.f, 0.f);
            #pragma unroll
            for (int g = 0; g < 4; ++g) sF4[t*5 + g] = z;
            #pragma unroll
            for (int a = 0; a < 8; ++a) sEWst[t*9 + a] = 0.f;
        }
        __syncthreads();

        // reduce: each owner sums its 4 p-values over a 32-vertex slice.
        // vv is warp-uniform -> ew read is an 8-scalar broadcast, feat read is
        // 4 consecutive float4s (conflict-free).
        const int v0 = slice * 32;
        #pragma unroll 4
        for (int i = 0; i < 32; ++i) {
            const int vv = v0 + i;
            const float  w = sEWst[vv*9 + aa];
            const float4 f = sF4[vv*5 + pg];
            acc.x += w * f.x; acc.y += w * f.y;
            acc.z += w * f.z; acc.w += w * f.w;
        }
        __syncthreads();
    }

    // cross-slice reduction (reuse sF4 as sRed[8][32])
    {
        float4* sRed = sF4;
        sRed[slice * 32 + owner] = acc;
        __syncthreads();
        if (t < 32) {
            float4 s = sRed[t];
            #pragma unroll
            for (int sl = 1; sl < 8; ++sl) {
                const float4 r = sRed[sl * 32 + t];
                s.x += r.x; s.y += r.y; s.z += r.z; s.w += r.w;
            }
            // owner t covers offset aa*16 + pg*4 == 4*t -> contiguous float4 store
            ((float4*)g_part)[blockIdx.x * 32 + t] = s;
            __threadfence();   // release
        }
        __syncthreads();
    }

    // =====================================================================
    // Grid barrier. GRID (=128) <= SM count, so every block is resident in
    // wave 1 regardless of occupancy -> no deadlock. Monotonic ticket makes
    // it correct across graph replays.
    // =====================================================================
    if (t == 0) {
        const unsigned ticket = atomicAdd(&g_count, 1u);
        const unsigned target = (ticket / (unsigned)GRID + 1u) * (unsigned)GRID;
        while (*(volatile unsigned*)&g_count < target) { __nanosleep(64); }
        __threadfence();       // acquire
    }
    __syncthreads();

    // =====================================================================
    // Phase B
    // =====================================================================
    if (t < 128) {
        float s = 0.f;
        #pragma unroll
        for (int sp = 0; sp < SPLIT; ++sp)
            s += g_part[(b * SPLIT + sp) * 128 + t];
        sAgg[t] = s * (1.0f / (float)NV);
    }
    __syncthreads();
    if (t < 128) {
        const int a = t >> 4, n = t & 15;
        float s = 0.f;
        #pragma unroll
        for (int p = 0; p < NP; ++p)
            s += sAgg[a*NP + p] * W_out[(a*NP + p)*NOUT + n];
        sM[a*NOUT + n] = s;
    }
    __syncthreads();

    for (int c = 0; c < NCH; ++c) {
        const int v = vbase + c * CH + t;
        float4* op = (float4*)(out + ((size_t)(b * NV + v)) * NOUT);

        if (v < nv) {
            const float4* dp = (const float4*)(data + ((size_t)(b * NV + v)) * NFEAT);
            const float4 x0 = dp[0], x1 = dp[1], x2 = dp[2], x3 = dp[3];
            float x[16];
            x[0]=x0.x;  x[1]=x0.y;  x[2]=x0.z;  x[3]=x0.w;
            x[4]=x1.x;  x[5]=x1.y;  x[6]=x1.z;  x[7]=x1.w;
            x[8]=x2.x;  x[9]=x2.y;  x[10]=x2.z; x[11]=x2.w;
            x[12]=x3.x; x[13]=x3.y; x[14]=x3.z; x[15]=x3.w;

            float ew[8];
            #pragma unroll
            for (int g = 0; g < 2; ++g) {
                float s0 = sbs[g*4+0], s1 = sbs[g*4+1];
                float s2 = sbs[g*4+2], s3 = sbs[g*4+3];
                #pragma unroll
                for (int f = 0; f < 16; ++f) {
                    const float4 w = sWs4[f][g];
                    s0 += x[f]*w.x; s1 += x[f]*w.y;
                    s2 += x[f]*w.z; s3 += x[f]*w.w;
                }
                ew[g*4+0] = __expf(-s0*s0);
                ew[g*4+1] = __expf(-s1*s1);
                ew[g*4+2] = __expf(-s2*s2);
                ew[g*4+3] = __expf(-s3*s3);
            }

            float4 o[4];
            #pragma unroll
            for (int j = 0; j < 4; ++j)
                o[j] = make_float4(sbo[j*4], sbo[j*4+1], sbo[j*4+2], sbo[j*4+3]);
            #pragma unroll
            for (int a = 0; a < NA; ++a) {
                const float w = ew[a];
                const float4* mrow = (const float4*)(sM + a * NOUT);
                #pragma unroll
                for (int j = 0; j < 4; ++j) {
                    const float4 m = mrow[j];
                    o[j].x += w * m.x; o[j].y += w * m.y;
                    o[j].z += w * m.z; o[j].w += w * m.w;
                }
            }
            op[0] = o[0]; op[1] = o[1]; op[2] = o[2]; op[3] = o[3];
        } else {
            const float4 z = make_float4(0.f, 0.f, 0.f, 0.f);
            op[0] = z; op[1] = z; op[2] = z; op[3] = z;
        }
    }
}

extern "C" void kernel_launch(void* const* d_in, const int* in_sizes, int n_in,
                              void* d_out, int out_size) {
    const float* data       = (const float*)d_in[0];
    const int*   num_vertex = (const int*)  d_in[1];
    const float* W_flr      = (const float*)d_in[2];
    const float* b_flr      = (const float*)d_in[3];
    const float* W_s        = (const float*)d_in[4];
    const float* b_s        = (const float*)d_in[5];
    const float* W_out      = (const float*)d_in[6];
    const float* b_out      = (const float*)d_in[7];
    float* out = (float*)d_out;

    garnet_fused<<<GRID, 256>>>(data, num_vertex, W_flr, b_flr,
                                W_s, b_s, W_out, b_out, out);
}

// round 4
// speedup vs baseline: 1.4429x; 1.4429x over previous
#include <cuda_runtime.h>

#define NB    64
#define NV    4096
#define NFEAT 16
#define NA    8
#define NP    16
#define NOUT  16
#define S1    16                 // splits per batch
#define CH    256                // vertices per block (= blockDim)
#define GRID1 (NB * S1)          // 1024 blocks

// Per-(b,split) partials of sum_v ew[v,a]*feat[v,p] (128 floats each).
// Every block writes its slot unconditionally -> no zeroing kernel needed.
__device__ float g_part[GRID1 * 128];

// ---------------------------------------------------------------------------
// k1: per-block partial aggregation over 256 vertices.
// ---------------------------------------------------------------------------
__global__ __launch_bounds__(256, 3) void k_aggregate(
    const float* __restrict__ data, const int* __restrict__ num_vertex,
    const float* __restrict__ W_flr, const float* __restrict__ b_flr,
    const float* __restrict__ W_s,   const float* __restrict__ b_s)
{
    __shared__ float4 sWf4[NFEAT][4];
    __shared__ float4 sWs4[NFEAT][2];
    __shared__ float  sbf[NP];
    __shared__ float  sbs[NA];
    __shared__ float4 sF4[CH * 5];       // feat staging (stride 5 float4); reused as sRed
    __shared__ float  sEW[CH * 9];       // ew staging (stride 9)

    const int t     = threadIdx.x;
    const int b     = blockIdx.x / S1;
    const int split = blockIdx.x % S1;
    const int nv    = num_vertex[b];
    const int vbase = split * CH;

    if (vbase >= nv) {                   // fully masked block: write zero partial
        if (t < 32)
            ((float4*)g_part)[blockIdx.x * 32 + t] = make_float4(0.f, 0.f, 0.f, 0.f);
        return;
    }

    if (t < 64) {
        sWf4[t >> 2][t & 3] = ((const float4*)W_flr)[t];
    } else if (t < 96) {
        const int u = t - 64;
        sWs4[u >> 1][u & 1] = ((const float4*)W_s)[u];
    } else if (t < 112) {
        sbf[t - 96] = b_flr[t - 96];
    } else if (t < 120) {
        sbs[t - 112] = b_s[t - 112];
    }
    __syncthreads();

    const int v = vbase + t;
    if (v < nv) {
        const float4* dp = (const float4*)(data + ((size_t)(b * NV + v)) * NFEAT);
        const float4 x0 = dp[0], x1 = dp[1], x2 = dp[2], x3 = dp[3];
        float x[16];
        x[0]=x0.x;  x[1]=x0.y;  x[2]=x0.z;  x[3]=x0.w;
        x[4]=x1.x;  x[5]=x1.y;  x[6]=x1.z;  x[7]=x1.w;
        x[8]=x2.x;  x[9]=x2.y;  x[10]=x2.z; x[11]=x2.w;
        x[12]=x3.x; x[13]=x3.y; x[14]=x3.z; x[15]=x3.w;

        #pragma unroll
        for (int g = 0; g < 4; ++g) {
            float s0 = sbf[g*4+0], s1 = sbf[g*4+1];
            float s2 = sbf[g*4+2], s3 = sbf[g*4+3];
            #pragma unroll
            for (int f = 0; f < 16; ++f) {
                const float4 w = sWf4[f][g];
                s0 += x[f]*w.x; s1 += x[f]*w.y;
                s2 += x[f]*w.z; s3 += x[f]*w.w;
            }
            sF4[t*5 + g] = make_float4(s0, s1, s2, s3);
        }
        #pragma unroll
        for (int g = 0; g < 2; ++g) {
            float s0 = sbs[g*4+0], s1 = sbs[g*4+1];
            float s2 = sbs[g*4+2], s3 = sbs[g*4+3];
            #pragma unroll
            for (int f = 0; f < 16; ++f) {
                const float4 w = sWs4[f][g];
                s0 += x[f]*w.x; s1 += x[f]*w.y;
                s2 += x[f]*w.z; s3 += x[f]*w.w;
            }
            sEW[t*9 + g*4+0] = __expf(-s0*s0);
            sEW[t*9 + g*4+1] = __expf(-s1*s1);
            sEW[t*9 + g*4+2] = __expf(-s2*s2);
            sEW[t*9 + g*4+3] = __expf(-s3*s3);
        }
    } else {
        const float4 z = make_float4(0.f, 0.f, 0.f, 0.f);
        #pragma unroll
        for (int g = 0; g < 4; ++g) sF4[t*5 + g] = z;
        #pragma unroll
        for (int a = 0; a < 8; ++a) sEW[t*9 + a] = 0.f;
    }
    __syncthreads();

    // 32 owners (aa = o>>2 in 0..7, pg = o&3) x 8 slices of 32 vertices.
    // vv is warp-uniform -> ew read = multi-broadcast, feat read = LDS.128.
    const int owner = t & 31;
    const int aa    = owner >> 2;
    const int pg    = owner & 3;
    const int slice = t >> 5;
    float4 acc = make_float4(0.f, 0.f, 0.f, 0.f);

    const int v0 = slice * 32;
    #pragma unroll 4
    for (int i = 0; i < 32; ++i) {
        const int vv = v0 + i;
        const float  w = sEW[vv*9 + aa];
        const float4 f = sF4[vv*5 + pg];
        acc.x += w * f.x; acc.y += w * f.y;
        acc.z += w * f.z; acc.w += w * f.w;
    }
    __syncthreads();

    // cross-slice reduction (reuse sF4 as sRed[8][32])
    float4* sRed = sF4;
    sRed[slice * 32 + owner] = acc;
    __syncthreads();
    if (t < 32) {
        float4 s = sRed[t];
        #pragma unroll
        for (int sl = 1; sl < 8; ++sl) {
            const float4 r = sRed[sl * 32 + t];
            s.x += r.x; s.y += r.y; s.z += r.z; s.w += r.w;
        }
        // owner t covers offset aa*16 + pg*4 == 4*t -> contiguous float4 store
        ((float4*)g_part)[blockIdx.x * 32 + t] = s;
    }
}

// ---------------------------------------------------------------------------
// k2: agg = sum of partials; M[a,n] = agg @ W_out slice; per-vertex output.
// ---------------------------------------------------------------------------
__global__ __launch_bounds__(256, 4) void k_output(
    const float* __restrict__ data, const int* __restrict__ num_vertex,
    const float* __restrict__ W_s, const float* __restrict__ b_s,
    const float* __restrict__ W_out, const float* __restrict__ b_out,
    float* __restrict__ out)
{
    __shared__ __align__(16) float sM[NA * NOUT];
    __shared__ float  sAgg[NA * NP];
    __shared__ float4 sWs4[NFEAT][2];
    __shared__ float  sbs[NA];
    __shared__ float  sbo[NOUT];

    const int t  = threadIdx.x;
    const int b  = blockIdx.x / S1;
    const int vb = (blockIdx.x % S1) * CH;
    const int nv = num_vertex[b];
    const int v  = vb + t;
    float4* op = (float4*)(out + ((size_t)(b * NV + v)) * NOUT);

    if (t < 128) {
        float s = 0.f;
        #pragma unroll
        for (int sp = 0; sp < S1; ++sp)
            s += g_part[(b * S1 + sp) * 128 + t];
        sAgg[t] = s * (1.0f / (float)NV);
    } else if (t < 160) {
        const int u = t - 128;
        sWs4[u >> 1][u & 1] = ((const float4*)W_s)[u];
    } else if (t < 168) {
        sbs[t - 160] = b_s[t - 160];
    } else if (t < 184) {
        sbo[t - 168] = b_out[t - 168];
    }
    __syncthreads();

    if (t < 128) {
        const int a = t >> 4, n = t & 15;
        float s = 0.f;
        #pragma unroll
        for (int p = 0; p < NP; ++p)
            s += sAgg[a*NP + p] * W_out[(a*NP + p)*NOUT + n];
        sM[a*NOUT + n] = s;
    }
    __syncthreads();

    if (v < nv) {
        const float4* dp = (const float4*)(data + ((size_t)(b * NV + v)) * NFEAT);
        const float4 x0 = dp[0], x1 = dp[1], x2 = dp[2], x3 = dp[3];
        float x[16];
        x[0]=x0.x;  x[1]=x0.y;  x[2]=x0.z;  x[3]=x0.w;
        x[4]=x1.x;  x[5]=x1.y;  x[6]=x1.z;  x[7]=x1.w;
        x[8]=x2.x;  x[9]=x2.y;  x[10]=x2.z; x[11]=x2.w;
        x[12]=x3.x; x[13]=x3.y; x[14]=x3.z; x[15]=x3.w;

        float ew[8];
        #pragma unroll
        for (int g = 0; g < 2; ++g) {
            float s0 = sbs[g*4+0], s1 = sbs[g*4+1];
            float s2 = sbs[g*4+2], s3 = sbs[g*4+3];
            #pragma unroll
            for (int f = 0; f < 16; ++f) {
                const float4 w = sWs4[f][g];
                s0 += x[f]*w.x; s1 += x[f]*w.y;
                s2 += x[f]*w.z; s3 += x[f]*w.w;
            }
            ew[g*4+0] = __expf(-s0*s0);
            ew[g*4+1] = __expf(-s1*s1);
            ew[g*4+2] = __expf(-s2*s2);
            ew[g*4+3] = __expf(-s3*s3);
        }

        float4 o[4];
        #pragma unroll
        for (int j = 0; j < 4; ++j)
            o[j] = make_float4(sbo[j*4], sbo[j*4+1], sbo[j*4+2], sbo[j*4+3]);
        #pragma unroll
        for (int a = 0; a < NA; ++a) {
            const float w = ew[a];
            const float4* mrow = (const float4*)(sM + a * NOUT);
            #pragma unroll
            for (int j = 0; j < 4; ++j) {
                const float4 m = mrow[j];
                o[j].x += w * m.x; o[j].y += w * m.y;
                o[j].z += w * m.z; o[j].w += w * m.w;
            }
        }
        op[0] = o[0]; op[1] = o[1]; op[2] = o[2]; op[3] = o[3];
    } else {
        const float4 z = make_float4(0.f, 0.f, 0.f, 0.f);
        op[0] = z; op[1] = z; op[2] = z; op[3] = z;
    }
}

extern "C" void kernel_launch(void* const* d_in, const int* in_sizes, int n_in,
                              void* d_out, int out_size) {
    const float* data       = (const float*)d_in[0];
    const int*   num_vertex = (const int*)  d_in[1];
    const float* W_flr      = (const float*)d_in[2];
    const float* b_flr      = (const float*)d_in[3];
    const float* W_s        = (const float*)d_in[4];
    const float* b_s        = (const float*)d_in[5];
    const float* W_out      = (const float*)d_in[6];
    const float* b_out      = (const float*)d_in[7];
    float* out = (float*)d_out;

    k_aggregate<<<GRID1, 256>>>(data, num_vertex, W_flr, b_flr, W_s, b_s);
    k_output<<<GRID1, 256>>>(data, num_vertex, W_s, b_s, W_out, b_out, out);
}

// round 5
// speedup vs baseline: 1.4715x; 1.0199x over previous
#include <cuda_runtime.h>

#define NB    64
#define NV    4096
#define NFEAT 16
#define NA    8
#define NP    16
#define NOUT  16
#define S1    16                 // splits per batch
#define CH    256                // vertices per block (= blockDim)
#define GRID1 (NB * S1)          // 1024 blocks

// Per-(b,split) partials of sum_v ew[v,a]*feat[v,p] (128 floats each).
// Every block writes its slot unconditionally -> no zeroing kernel needed.
__device__ float g_part[GRID1 * 128];

// ---------------------------------------------------------------------------
// k1: per-block partial aggregation over 256 vertices.
// ---------------------------------------------------------------------------
__global__ __launch_bounds__(256, 4) void k_aggregate(
    const float* __restrict__ data, const int* __restrict__ num_vertex,
    const float* __restrict__ W_flr, const float* __restrict__ b_flr,
    const float* __restrict__ W_s,   const float* __restrict__ b_s)
{
    __shared__ float4 sWf4[NFEAT][4];
    __shared__ float4 sWs4[NFEAT][2];
    __shared__ float  sbf[NP];
    __shared__ float  sbs[NA];
    // per-vertex staging row: [0..3] = feat (4 float4), [4..5] = ew (2 float4)
    // row stride 6 float4 = 24 floats; reads are uniform-row -> broadcast, conflict-free
    __shared__ float4 sStage[CH * 6];

    const int t     = threadIdx.x;
    const int b     = blockIdx.x / S1;
    const int split = blockIdx.x % S1;
    const int nv    = num_vertex[b];
    const int vbase = split * CH;

    if (vbase >= nv) {                   // fully masked block: write zero partial
        if (t < 32)
            ((float4*)g_part)[blockIdx.x * 32 + t] = make_float4(0.f, 0.f, 0.f, 0.f);
        return;
    }

    if (t < 64) {
        sWf4[t >> 2][t & 3] = ((const float4*)W_flr)[t];
    } else if (t < 96) {
        const int u = t - 64;
        sWs4[u >> 1][u & 1] = ((const float4*)W_s)[u];
    } else if (t < 112) {
        sbf[t - 96] = b_flr[t - 96];
    } else if (t < 120) {
        sbs[t - 112] = b_s[t - 112];
    }
    __syncthreads();

    const int v = vbase + t;
    if (v < nv) {
        const float4* dp = (const float4*)(data + ((size_t)(b * NV + v)) * NFEAT);
        const float4 x0 = dp[0], x1 = dp[1], x2 = dp[2], x3 = dp[3];
        float x[16];
        x[0]=x0.x;  x[1]=x0.y;  x[2]=x0.z;  x[3]=x0.w;
        x[4]=x1.x;  x[5]=x1.y;  x[6]=x1.z;  x[7]=x1.w;
        x[8]=x2.x;  x[9]=x2.y;  x[10]=x2.z; x[11]=x2.w;
        x[12]=x3.x; x[13]=x3.y; x[14]=x3.z; x[15]=x3.w;

        #pragma unroll
        for (int g = 0; g < 4; ++g) {
            float s0 = sbf[g*4+0], s1 = sbf[g*4+1];
            float s2 = sbf[g*4+2], s3 = sbf[g*4+3];
            #pragma unroll
            for (int f = 0; f < 16; ++f) {
                const float4 w = sWf4[f][g];
                s0 += x[f]*w.x; s1 += x[f]*w.y;
                s2 += x[f]*w.z; s3 += x[f]*w.w;
            }
            sStage[t*6 + g] = make_float4(s0, s1, s2, s3);
        }
        #pragma unroll
        for (int g = 0; g < 2; ++g) {
            float s0 = sbs[g*4+0], s1 = sbs[g*4+1];
            float s2 = sbs[g*4+2], s3 = sbs[g*4+3];
            #pragma unroll
            for (int f = 0; f < 16; ++f) {
                const float4 w = sWs4[f][g];
                s0 += x[f]*w.x; s1 += x[f]*w.y;
                s2 += x[f]*w.z; s3 += x[f]*w.w;
            }
            sStage[t*6 + 4 + g] = make_float4(__expf(-s0*s0), __expf(-s1*s1),
                                              __expf(-s2*s2), __expf(-s3*s3));
        }
    } else {
        const float4 z = make_float4(0.f, 0.f, 0.f, 0.f);
        #pragma unroll
        for (int g = 0; g < 6; ++g) sStage[t*6 + g] = z;
    }
    __syncthreads();

    // 32 owners (aa = o>>2 in 0..7, pg = o&3) x 8 slices of 32 vertices.
    const int owner = t & 31;
    const int aa    = owner >> 2;
    const int pg    = owner & 3;
    const int slice = t >> 5;
    const float* sS = (const float*)sStage;
    float4 acc = make_float4(0.f, 0.f, 0.f, 0.f);

    const int v0 = slice * 32;
    #pragma unroll 4
    for (int i = 0; i < 32; ++i) {
        const int vv = v0 + i;
        const float  w = sS[vv*24 + 16 + aa];      // ew[aa], broadcast
        const float4 f = sStage[vv*6 + pg];        // feat group, multicast
        acc.x += w * f.x; acc.y += w * f.y;
        acc.z += w * f.z; acc.w += w * f.w;
    }
    __syncthreads();

    // cross-slice reduction (reuse sStage as sRed[8][32])
    float4* sRed = sStage;
    sRed[slice * 32 + owner] = acc;
    __syncthreads();
    if (t < 32) {
        float4 s = sRed[t];
        #pragma unroll
        for (int sl = 1; sl < 8; ++sl) {
            const float4 r = sRed[sl * 32 + t];
            s.x += r.x; s.y += r.y; s.z += r.z; s.w += r.w;
        }
        // owner t covers element offset aa*16 + pg*4 == 4*t -> contiguous float4
        ((float4*)g_part)[blockIdx.x * 32 + t] = s;
    }
}

// ---------------------------------------------------------------------------
// k2: agg = sum of partials; M[a,n] = agg @ W_out slice; per-vertex output.
// ---------------------------------------------------------------------------
__global__ __launch_bounds__(256, 4) void k_output(
    const float* __restrict__ data, const int* __restrict__ num_vertex,
    const float* __restrict__ W_s, const float* __restrict__ b_s,
    const float* __restrict__ W_out, const float* __restrict__ b_out,
    float* __restrict__ out)
{
    __shared__ __align__(16) float sM[NA * NOUT];
    __shared__ float4 sAgg4[32];          // agg[a*16+p] as 32 float4
    __shared__ float4 sWs4[NFEAT][2];
    __shared__ float  sbs[NA];
    __shared__ float  sbo[NOUT];

    const int t  = threadIdx.x;
    const int b  = blockIdx.x / S1;
    const int vb = (blockIdx.x % S1) * CH;
    const int nv = num_vertex[b];
    const int v  = vb + t;
    float4* op = (float4*)(out + ((size_t)(b * NV + v)) * NOUT);
    const float4 z = make_float4(0.f, 0.f, 0.f, 0.f);

    if (vb >= nv) {                        // fully masked block: zeros only
        op[0] = z; op[1] = z; op[2] = z; op[3] = z;
        return;
    }

    // Hoist vertex data loads: independent of the prologue, overlap its L2 trips.
    const bool valid = (v < nv);
    float4 x0 = z, x1 = z, x2 = z, x3 = z;
    if (valid) {
        const float4* dp = (const float4*)(data + ((size_t)(b * NV + v)) * NFEAT);
        x0 = dp[0]; x1 = dp[1]; x2 = dp[2]; x3 = dp[3];
    }

    // Prologue: 32 threads x 16 coalesced float4 loads (one L2 trip, full MLP).
    if (t < 32) {
        float4 s = z;
        #pragma unroll
        for (int sp = 0; sp < S1; ++sp) {
            const float4 r = ((const float4*)g_part)[(b * S1 + sp) * 32 + t];
            s.x += r.x; s.y += r.y; s.z += r.z; s.w += r.w;
        }
        const float inv = 1.0f / (float)NV;
        s.x *= inv; s.y *= inv; s.z *= inv; s.w *= inv;
        sAgg4[t] = s;
    } else if (t < 64) {
        const int u = t - 32;
        sWs4[u >> 1][u & 1] = ((const float4*)W_s)[u];
    } else if (t < 72) {
        sbs[t - 64] = b_s[t - 64];
    } else if (t < 88) {
        sbo[t - 72] = b_out[t - 72];
    }
    __syncthreads();

    if (t < 128) {
        const int a = t >> 4, n = t & 15;
        const float* agg = (const float*)sAgg4;   // agg[a*16+p]
        float s = 0.f;
        #pragma unroll
        for (int p = 0; p < NP; ++p)
            s += agg[a*NP + p] * W_out[(a*NP + p)*NOUT + n];
        sM[t] = s;
    }
    __syncthreads();

    if (valid) {
        float x[16];
        x[0]=x0.x;  x[1]=x0.y;  x[2]=x0.z;  x[3]=x0.w;
        x[4]=x1.x;  x[5]=x1.y;  x[6]=x1.z;  x[7]=x1.w;
        x[8]=x2.x;  x[9]=x2.y;  x[10]=x2.z; x[11]=x2.w;
        x[12]=x3.x; x[13]=x3.y; x[14]=x3.z; x[15]=x3.w;

        float ew[8];
        #pragma unroll
        for (int g = 0; g < 2; ++g) {
            float s0 = sbs[g*4+0], s1 = sbs[g*4+1];
            float s2 = sbs[g*4+2], s3 = sbs[g*4+3];
            #pragma unroll
            for (int f = 0; f < 16; ++f) {
                const float4 w = sWs4[f][g];
                s0 += x[f]*w.x; s1 += x[f]*w.y;
                s2 += x[f]*w.z; s3 += x[f]*w.w;
            }
            ew[g*4+0] = __expf(-s0*s0);
            ew[g*4+1] = __expf(-s1*s1);
            ew[g*4+2] = __expf(-s2*s2);
            ew[g*4+3] = __expf(-s3*s3);
        }

        float4 o[4];
        #pragma unroll
        for (int j = 0; j < 4; ++j)
            o[j] = make_float4(sbo[j*4], sbo[j*4+1], sbo[j*4+2], sbo[j*4+3]);
        #pragma unroll
        for (int a = 0; a < NA; ++a) {
            const float w = ew[a];
            const float4* mrow = (const float4*)(sM + a * NOUT);
            #pragma unroll
            for (int j = 0; j < 4; ++j) {
                const float4 m = mrow[j];
                o[j].x += w * m.x; o[j].y += w * m.y;
                o[j].z += w * m.z; o[j].w += w * m.w;
            }
        }
        op[0] = o[0]; op[1] = o[1]; op[2] = o[2]; op[3] = o[3];
    } else {
        op[0] = z; op[1] = z; op[2] = z; op[3] = z;
    }
}

extern "C" void kernel_launch(void* const* d_in, const int* in_sizes, int n_in,
                              void* d_out, int out_size) {
    const float* data       = (const float*)d_in[0];
    const int*   num_vertex = (const int*)  d_in[1];
    const float* W_flr      = (const float*)d_in[2];
    const float* b_flr      = (const float*)d_in[3];
    const float* W_s        = (const float*)d_in[4];
    const float* b_s        = (const float*)d_in[5];
    const float* W_out      = (const float*)d_in[6];
    const float* b_out      = (const float*)d_in[7];
    float* out = (float*)d_out;

    k_aggregate<<<GRID1, 256>>>(data, num_vertex, W_flr, b_flr, W_s, b_s);
    k_output<<<GRID1, 256>>>(data, num_vertex, W_s, b_s, W_out, b_out, out);
}